// round 17
// baseline (speedup 1.0000x reference)
#include <cuda_runtime.h>
#include <cuda_fp16.h>
#include <stdint.h>

// ============================================================================
// Problem constants / layout
// ============================================================================
#define D 128
#define TILE_M 64                 // persistent tile: 64 edges x 128 cols

#define ROW_BYTES  272            // padded fp16 row: stride%128=16 -> ldmatrix conflict-free
#define STAGE_STRIDE 132          // fp32 stage row stride (528B: bank-rotating)

// SMEM layout (bytes), distinct regions (3 barriers/tile):
//   [0, 17408)       A fp16 tile (64 x 272B)
//   [17408, 51200)   fp32 stage 64 x 132
//   [51200]          bias (128 floats)
//   [51712]          dst slice (64 ints)
#define OFF_A      0
#define OFF_STAGE  17408
#define OFF_BIAS   51200
#define OFF_DST    51712
#define SMEM_TOTAL 51968
// 52KB/CTA x 2 CTAs -> L1D carveout ~124KB keeps the 32KB W table resident.

// ============================================================================
// PTX helpers (base ISA only: ldmatrix / mma.sync)
// ============================================================================
__device__ __forceinline__ uint32_t smem_to_u32(const void* p) {
    uint32_t a;
    asm("{ .reg .u64 t; cvta.to.shared.u64 t, %1; cvt.u32.u64 %0, t; }" : "=r"(a) : "l"(p));
    return a;
}

#define LDSM4(r, addr) \
    asm volatile("ldmatrix.sync.aligned.m8n8.x4.shared.b16 {%0,%1,%2,%3}, [%4];" \
        : "=r"((r)[0]), "=r"((r)[1]), "=r"((r)[2]), "=r"((r)[3]) : "r"(addr))

#define MMA_F16(c, a, b0, b1) \
    asm volatile("mma.sync.aligned.m16n8k16.row.col.f32.f16.f16.f32 " \
        "{%0,%1,%2,%3},{%4,%5,%6,%7},{%8,%9},{%0,%1,%2,%3};" \
        : "+f"((c)[0]), "+f"((c)[1]), "+f"((c)[2]), "+f"((c)[3]) \
        : "r"((a)[0]), "r"((a)[1]), "r"((a)[2]), "r"((a)[3]), \
          "r"(b0), "r"(b1))

// ============================================================================
// W in B-fragment order: [kstep(8)][n8tile(16)][lane(32)] -> uint2 {b0, b1}
// Single fp16 table (measured rel_err 1.64e-4). Each warp hoists nt=0
// (16 regs); nt=1..3 stream from this L1-resident table.
// ============================================================================
__device__ uint2 g_Wf[8 * 16 * 32];  // 32 KB

__device__ __forceinline__ uint32_t packf16(float x0, float x1) {
    __half h0 = __float2half_rn(x0);
    __half h1 = __float2half_rn(x1);
    return (uint32_t)__half_as_ushort(h0) | ((uint32_t)__half_as_ushort(h1) << 16);
}

// ============================================================================
// Kernel 0 (merged prep): init out to -inf AND pack W into fp16 fragments.
// ============================================================================
__global__ void prep_kernel(int4* __restrict__ out, int n4, const float* __restrict__ W) {
    const int init_blocks = (n4 + 255) / 256;
    if ((int)blockIdx.x < init_blocks) {
        int i = blockIdx.x * 256 + threadIdx.x;
        if (i < n4) {
            const int m = 0xff800000;  // -inf
            out[i] = make_int4(m, m, m, m);
        }
    } else {
        int i = (blockIdx.x - init_blocks) * 256 + threadIdx.x;  // 0 .. 4095
        if (i < 8 * 16 * 32) {
            int lane = i & 31;
            int n8t  = (i >> 5) & 15;
            int kst  = i >> 9;
            int n  = n8t * 8 + (lane >> 2);
            int k0 = kst * 16 + (lane & 3) * 2;
            const float* Wr = W + (size_t)n * D;
            g_Wf[i] = make_uint2(packf16(Wr[k0],     Wr[k0 + 1]),
                                 packf16(Wr[k0 + 8], Wr[k0 + 9]));
        }
    }
}

// ============================================================================
// Kernel 1: PERSISTENT fused GEMM + scatter-max, TILE_M=64.
// - Cross-tile src prefetch in REGISTERS (no SMEM landing buffer: kills the
//   256KB/tile buf round trip that was 50% of all L1/SMEM bytes in R16).
// - Partial W hoist: nt=0 in regs, nt=1..3 from L1-resident table (fits the
//   128-reg budget alongside pend[8] + acc).
// - Staged scatter: every atomicMax instr = 1 dst row x 128B = 1 wavefront.
// ============================================================================
__global__ __launch_bounds__(256, 2) void fused_kernel(
    const float* __restrict__ src,
    const float* __restrict__ b,
    const int* __restrict__ dst_idx,   // int32 (JAX x64-disabled downcasts int64)
    int* __restrict__ out,
    int E, int N, int tiles)
{
    extern __shared__ __align__(16) char smem[];
    float* bias_s = reinterpret_cast<float*>(smem + OFF_BIAS);
    int*   dst_s  = reinterpret_cast<int*>(smem + OFF_DST);

    const int tid  = threadIdx.x;
    const int wid  = tid >> 5;
    const int lane = tid & 31;

    const int m_base = (wid & 1) * 32;    // warp M tile (rows 0..63)
    const int n_base = (wid >> 1) * 32;   // warp N tile (cols 0..127)
    const int nb8    = n_base >> 3;       // first n8 tile index
    const int cb     = 2 * (lane & 3);

    if (tid < D) bias_s[tid] = b[tid];

    // ---- partial W hoist: nt=0 fragments into registers (16 regs) ----
    uint2 W0[8];
    #pragma unroll
    for (int k = 0; k < 8; k++)
        W0[k] = g_Wf[(k * 16 + nb8) * 32 + lane];

    const uint32_t sb = smem_to_u32(smem);
    const uint32_t aBase = sb + OFF_A
        + (uint32_t)(m_base + (lane & 15)) * ROW_BYTES + (uint32_t)(lane >> 4) * 16;

    const float4* srcT = reinterpret_cast<const float4*>(src);
    const float4 z4 = make_float4(0.f, 0.f, 0.f, 0.f);

    // ---- initial prefetch: tile blockIdx.x (64 rows = 2048 float4) ----
    float4 pend[8];
    {
        int tb = blockIdx.x * TILE_M;
        int rm = min(TILE_M, E - tb);
        #pragma unroll
        for (int u = 0; u < 8; u++) {
            int i = tid + u * 256;           // 0..2047 -> row = i>>5 in 0..63
            pend[u] = ((i >> 5) < rm) ? __ldcs(&srcT[(size_t)tb * 32 + i]) : z4;
        }
    }

    for (int t = blockIdx.x; t < tiles; t += gridDim.x) {
        const int tile_base = t * TILE_M;
        const int rem = min(TILE_M, E - tile_base);

        __syncthreads();  // previous tile's stage fully scattered; A free

        // ---- drain pending regs -> fp16 A tile in SMEM; load dst slice ----
        #pragma unroll
        for (int u = 0; u < 8; u++) {
            int i = tid + u * 256;
            int row = i >> 5;
            int col4 = i & 31;
            uint2 h = make_uint2(packf16(pend[u].x, pend[u].y),
                                 packf16(pend[u].z, pend[u].w));
            *reinterpret_cast<uint2*>(smem + OFF_A + (size_t)row * ROW_BYTES + (size_t)col4 * 8) = h;
        }
        if (tid < TILE_M) dst_s[tid] = (tid < rem) ? dst_idx[tile_base + tid] : -1;

        __syncthreads();  // A tile + dst_s ready

        // ---- issue next tile's loads NOW (in flight during MMA+epilogue) ----
        {
            int tn = t + gridDim.x;
            if (tn < tiles) {
                int tbn = tn * TILE_M;
                int rmn = min(TILE_M, E - tbn);
                #pragma unroll
                for (int u = 0; u < 8; u++) {
                    int i = tid + u * 256;
                    pend[u] = ((i >> 5) < rmn) ? __ldcs(&srcT[(size_t)tbn * 32 + i]) : z4;
                }
            }
        }

        // ---- MMA: K=128 in 8 k16 steps; nt=0 W from regs, nt=1..3 from L1 ----
        float acc[2][4][4];
        #pragma unroll
        for (int mt = 0; mt < 2; mt++)
            #pragma unroll
            for (int nt = 0; nt < 4; nt++)
                #pragma unroll
                for (int c = 0; c < 4; c++) acc[mt][nt][c] = 0.f;

        #pragma unroll
        for (int k = 0; k < 8; k++) {
            const int fbase = (k * 16 + nb8) * 32 + lane;
            uint2 B1 = g_Wf[fbase + 1 * 32];
            uint2 B2 = g_Wf[fbase + 2 * 32];
            uint2 B3 = g_Wf[fbase + 3 * 32];
            uint32_t a[2][4];
            #pragma unroll
            for (int mt = 0; mt < 2; mt++)
                LDSM4(a[mt], aBase + (uint32_t)mt * 16 * ROW_BYTES + (uint32_t)k * 32);
            #pragma unroll
            for (int mt = 0; mt < 2; mt++) {
                MMA_F16(acc[mt][0], a[mt], W0[k].x, W0[k].y);
                MMA_F16(acc[mt][1], a[mt], B1.x, B1.y);
                MMA_F16(acc[mt][2], a[mt], B2.x, B2.y);
                MMA_F16(acc[mt][3], a[mt], B3.x, B3.y);
            }
        }

        // ---- epilogue: bias + relu -> fp32 stage (separate region, no sync) ----
        {
            float* stage = reinterpret_cast<float*>(smem + OFF_STAGE);
            const int r0 = m_base + (lane >> 2);
            #pragma unroll
            for (int mt = 0; mt < 2; mt++) {
                #pragma unroll
                for (int nt = 0; nt < 4; nt++) {
                    int col = n_base + nt * 8 + cb;
                    float bv0 = bias_s[col], bv1 = bias_s[col + 1];
                    int rr = r0 + mt * 16;
                    *reinterpret_cast<float2*>(&stage[rr * STAGE_STRIDE + col]) =
                        make_float2(fmaxf(acc[mt][nt][0] + bv0, 0.f),
                                    fmaxf(acc[mt][nt][1] + bv1, 0.f));
                    *reinterpret_cast<float2*>(&stage[(rr + 8) * STAGE_STRIDE + col]) =
                        make_float2(fmaxf(acc[mt][nt][2] + bv0, 0.f),
                                    fmaxf(acc[mt][nt][3] + bv1, 0.f));
                }
            }
        }
        __syncthreads();  // stage complete (cross-warp rows)

        // ---- scatter: warp-per-row, 32 contiguous cols per atomic instr ----
        {
            const float* stage = reinterpret_cast<const float*>(smem + OFF_STAGE);
            for (int rr = wid; rr < rem; rr += 8) {
                int dst = dst_s[rr];
                if ((unsigned)dst >= (unsigned)N) continue;
                int* op = out + (size_t)dst * D;
                #pragma unroll
                for (int kk = 0; kk < 4; kk++) {
                    int col = lane + kk * 32;  // 128B contiguous = 1 wavefront
                    // relu => v >= 0; init 0xFF800000 => signed-int max == float max
                    atomicMax(op + col, __float_as_int(stage[rr * STAGE_STRIDE + col]));
                }
            }
        }
    }
}

// ============================================================================
// Launch
// ============================================================================
extern "C" void kernel_launch(void* const* d_in, const int* in_sizes, int n_in,
                              void* d_out, int out_size) {
    const float* src     = (const float*)d_in[0];
    const float* W       = (const float*)d_in[1];
    const float* b       = (const float*)d_in[2];
    const int*   dst     = (const int*)d_in[3];   // int32 on device

    const int E = in_sizes[0] / D;
    const int N = out_size / D;
    const int tiles = (E + TILE_M - 1) / TILE_M;

    // 0: merged prep (init out to -inf + pack W fp16 fragments)
    int n4 = out_size / 4;
    int init_blocks = (n4 + 255) / 256;
    int frag_blocks = (8 * 16 * 32 + 255) / 256;
    prep_kernel<<<init_blocks + frag_blocks, 256>>>((int4*)d_out, n4, W);

    // 1: persistent fused GEMM + scatter-max (2 CTAs/SM x 148 SMs)
    int grid = 296;
    if (grid > tiles) grid = tiles;
    cudaFuncSetAttribute(fused_kernel, cudaFuncAttributeMaxDynamicSharedMemorySize,
                         SMEM_TOTAL);
    fused_kernel<<<grid, 256, SMEM_TOTAL>>>(src, b, dst, (int*)d_out, E, N, tiles);
}